// round 7
// baseline (speedup 1.0000x reference)
#include <cuda_runtime.h>
#include <cstdint>
#include <cstddef>

#define BB 32
#define NNODE 1024
#define DD 512

__device__ float g_At [(size_t)BB * NNODE * NNODE];  // rna-rounded transpose of sc
__device__ float g_P  [(size_t)BB * NNODE * DD];     // Y1d / Y2d (node-major)
__device__ float g_Q  [(size_t)BB * NNODE * DD];     // H1 / H2
__device__ float g_W1t[DD * NNODE];
__device__ float g_W2t[DD * DD];
__device__ float g_dis[BB * NNODE];

__device__ __forceinline__ uint32_t smem_u32(const void* p) {
    uint32_t a;
    asm("{ .reg .u64 t; cvta.to.shared.u64 t, %1; cvt.u32.u64 %0, t; }" : "=r"(a) : "l"(p));
    return a;
}
__device__ __forceinline__ float rna_tf32(float x) {
    uint32_t r; asm("cvt.rna.tf32.f32 %0, %1;" : "=r"(r) : "f"(x));
    return __uint_as_float(r);
}
__device__ __forceinline__ uint32_t rna_tf32_u(uint32_t x) {
    uint32_t r; asm("cvt.rna.tf32.f32 %0, %1;" : "=r"(r) : "f"(__uint_as_float(x)));
    return r;
}
__device__ __forceinline__ void cp16(uint32_t s, const void* g) {
    asm volatile("cp.async.cg.shared.global [%0], [%1], 16;" :: "r"(s), "l"(g));
}
__device__ __forceinline__ uint32_t lds32(uint32_t a) {
    uint32_t v; asm volatile("ld.shared.b32 %0, [%1];" : "=r"(v) : "r"(a)); return v;
}

static constexpr int A_STRIDE = 36;     // pad 4 -> conflict-free frags
static constexpr int BK_STRIDE = 132;   // [32][132] for k-major B
static constexpr int ATILE_B = 128 * A_STRIDE * 4;   // 18432
static constexpr int STG = 2 * ATILE_B;              // 36864 per stage
static constexpr int SMEM_BYTES = 2 * STG;           // 73728

// ---------------------------------------------------------------------------
// TF32 mma.sync GEMM: CTA tile 128x128, K-chunk 32, 8 warps (2x4), warp 64x32.
// BKMAJ=false: B source row-major [N][K]. true: [K][N] (node-major).
// RNA_A: round A fragments to tf32 in-register (A source not pre-rounded).
// ---------------------------------------------------------------------------
template<bool BKMAJ, bool RELU, bool ROUND, bool HASBIAS, bool RNA_A>
__global__ __launch_bounds__(256, 2)
void mma_gemm(const float* __restrict__ Ap, const float* __restrict__ Bp,
              float* __restrict__ Cp, const float* __restrict__ disv,
              const float* __restrict__ bias,
              int K, int lda, int ldb, int ldc,
              size_t sA, size_t sB, size_t sC, size_t sD)
{
    extern __shared__ char smem[];
    const uint32_t sbase = smem_u32(smem);
    const int tid = threadIdx.x;
    const int wid = tid >> 5;
    const int lane = tid & 31;
    const int wm = wid >> 2;
    const int wn = wid & 3;
    const int lrow = lane >> 2;
    const int lcol = lane & 3;
    const int bz = blockIdx.z;
    const int m0 = blockIdx.y * 128;
    const int n0 = blockIdx.x * 128;

    Ap += (size_t)bz * sA;
    Bp += (size_t)bz * sB;
    Cp += (size_t)bz * sC;
    disv += (size_t)bz * sD;

    const int S = K / 32;

    auto load_stage = [&](int k0, uint32_t soff) {
        #pragma unroll
        for (int p = 0; p < 4; p++) {
            int id = tid + 256 * p;
            int row = id >> 3, c = id & 7;
            cp16(sbase + soff + (uint32_t)(row * A_STRIDE + c * 4) * 4,
                 Ap + (size_t)(m0 + row) * lda + k0 + c * 4);
        }
        if (!BKMAJ) {
            #pragma unroll
            for (int p = 0; p < 4; p++) {
                int id = tid + 256 * p;
                int row = id >> 3, c = id & 7;
                cp16(sbase + soff + ATILE_B + (uint32_t)(row * A_STRIDE + c * 4) * 4,
                     Bp + (size_t)(n0 + row) * ldb + k0 + c * 4);
            }
        } else {
            #pragma unroll
            for (int p = 0; p < 4; p++) {
                int id = tid + 256 * p;
                int krow = id >> 5, c = id & 31;
                cp16(sbase + soff + ATILE_B + (uint32_t)(krow * BK_STRIDE + c * 4) * 4,
                     Bp + (size_t)(k0 + krow) * ldb + n0 + c * 4);
            }
        }
        asm volatile("cp.async.commit_group;" ::: "memory");
    };

    load_stage(0, 0);
    if (S > 1) load_stage(32, STG);

    float acc[4][4][4];
    #pragma unroll
    for (int mi = 0; mi < 4; mi++)
        #pragma unroll
        for (int ni = 0; ni < 4; ni++)
            #pragma unroll
            for (int q = 0; q < 4; q++) acc[mi][ni][q] = 0.f;

    for (int s = 0; s < S; s++) {
        if (s + 1 < S) asm volatile("cp.async.wait_group 1;" ::: "memory");
        else           asm volatile("cp.async.wait_group 0;" ::: "memory");
        __syncthreads();

        const uint32_t aB = sbase + (uint32_t)(s & 1) * STG;
        const uint32_t bB = aB + ATILE_B;

        #pragma unroll
        for (int kk = 0; kk < 4; kk++) {
            uint32_t a[4][4];
            #pragma unroll
            for (int mi = 0; mi < 4; mi++) {
                int m = wm * 64 + mi * 16 + lrow;
                uint32_t ad = aB + (uint32_t)(m * A_STRIDE + kk * 8 + lcol) * 4;
                a[mi][0] = lds32(ad);
                a[mi][1] = lds32(ad + 8 * A_STRIDE * 4);
                a[mi][2] = lds32(ad + 16);
                a[mi][3] = lds32(ad + 8 * A_STRIDE * 4 + 16);
                if (RNA_A) {
                    a[mi][0] = rna_tf32_u(a[mi][0]);
                    a[mi][1] = rna_tf32_u(a[mi][1]);
                    a[mi][2] = rna_tf32_u(a[mi][2]);
                    a[mi][3] = rna_tf32_u(a[mi][3]);
                }
            }
            #pragma unroll
            for (int ni = 0; ni < 4; ni++) {
                uint32_t b0, b1;
                if (!BKMAJ) {
                    int n = wn * 32 + ni * 8 + lrow;
                    uint32_t bd = bB + (uint32_t)(n * A_STRIDE + kk * 8 + lcol) * 4;
                    b0 = lds32(bd);
                    b1 = lds32(bd + 16);
                } else {
                    uint32_t bd = bB + (uint32_t)((kk * 8 + lcol) * BK_STRIDE
                                                  + wn * 32 + ni * 8 + lrow) * 4;
                    b0 = lds32(bd);
                    b1 = lds32(bd + 4 * BK_STRIDE * 4);
                }
                #pragma unroll
                for (int mi = 0; mi < 4; mi++) {
                    asm volatile(
                        "mma.sync.aligned.m16n8k8.row.col.f32.tf32.tf32.f32 "
                        "{%0,%1,%2,%3}, {%4,%5,%6,%7}, {%8,%9}, {%0,%1,%2,%3};"
                        : "+f"(acc[mi][ni][0]), "+f"(acc[mi][ni][1]),
                          "+f"(acc[mi][ni][2]), "+f"(acc[mi][ni][3])
                        : "r"(a[mi][0]), "r"(a[mi][1]), "r"(a[mi][2]), "r"(a[mi][3]),
                          "r"(b0), "r"(b1));
                }
            }
        }
        __syncthreads();
        if (s + 2 < S) load_stage((s + 2) * 32, (uint32_t)(s & 1) * STG);
    }

    #pragma unroll
    for (int mi = 0; mi < 4; mi++) {
        const int ml = m0 + wm * 64 + mi * 16 + lrow;
        const float d0 = disv[ml];
        const float d1 = disv[ml + 8];
        #pragma unroll
        for (int ni = 0; ni < 4; ni++) {
            const int n = n0 + wn * 32 + ni * 8 + 2 * lcol;
            float bx = 0.f, by = 0.f;
            if (HASBIAS) { bx = bias[n]; by = bias[n + 1]; }
            float v0 = acc[mi][ni][0] * d0 + bx;
            float v1 = acc[mi][ni][1] * d0 + by;
            float v2 = acc[mi][ni][2] * d1 + bx;
            float v3 = acc[mi][ni][3] * d1 + by;
            if (RELU) {
                v0 = fmaxf(v0, 0.f); v1 = fmaxf(v1, 0.f);
                v2 = fmaxf(v2, 0.f); v3 = fmaxf(v3, 0.f);
            }
            if (ROUND) {
                v0 = rna_tf32(v0); v1 = rna_tf32(v1);
                v2 = rna_tf32(v2); v3 = rna_tf32(v3);
            }
            *(float2*)&Cp[(size_t)ml * ldc + n] = make_float2(v0, v1);
            *(float2*)&Cp[(size_t)(ml + 8) * ldc + n] = make_float2(v2, v3);
        }
    }
}

// ---------------------------------------------------------------------------
// zero zp (out z_pooled region) and dis accumulator (in-graph, every replay)
// ---------------------------------------------------------------------------
__global__ void zero2_kernel(float* a, int na, float* c, int nc)
{
    int i = blockIdx.x * 256 + threadIdx.x;
    if (i < na) a[i] = 0.f;
    if (i < nc) c[i] = 0.f;
}

// transpose with rna rounding + column-sum accumulation (for sc -> At + deg)
__global__ void transpose_rna_cs(const float* __restrict__ src, float* __restrict__ dst,
                                 float* __restrict__ dacc)
{
    __shared__ float t[32][33];
    __shared__ float cs[32];
    const size_t zoff = (size_t)blockIdx.z * NNODE * NNODE;
    src += zoff;
    dst += zoff;
    const int r0 = blockIdx.y * 32, c0 = blockIdx.x * 32;
    const int tx = threadIdx.x, ty = threadIdx.y;
    float v[4];
    #pragma unroll
    for (int q = 0; q < 4; q++) {
        v[q] = src[(size_t)(r0 + ty + q * 8) * NNODE + c0 + tx];
        t[ty + q * 8][tx] = v[q];
    }
    if (ty == 0) cs[tx] = 0.f;
    __syncthreads();
    atomicAdd(&cs[tx], ((v[0] + v[1]) + (v[2] + v[3])));
    #pragma unroll
    for (int q = 0; q < 4; q++)
        dst[(size_t)(c0 + ty + q * 8) * NNODE + r0 + tx] = rna_tf32(t[tx][ty + q * 8]);
    __syncthreads();
    if (ty == 0) atomicAdd(&dacc[(size_t)blockIdx.z * NNODE + c0 + tx], cs[tx]);
}

__global__ void rsqrt_fin(float* __restrict__ dis)
{
    int i = blockIdx.x * 256 + threadIdx.x;
    float s = dis[i];
    dis[i] = (s > 0.f) ? rsqrtf(s) : 0.f;
}

// plain weight transpose + round (small)
__global__ void transpose_rna_w(const float* __restrict__ src, float* __restrict__ dst,
                                int R, int C)
{
    __shared__ float t[32][33];
    const int r0 = blockIdx.y * 32, c0 = blockIdx.x * 32;
    const int tx = threadIdx.x, ty = threadIdx.y;
    #pragma unroll
    for (int q = 0; q < 4; q++)
        t[ty + q * 8][tx] = src[(size_t)(r0 + ty + q * 8) * C + c0 + tx];
    __syncthreads();
    #pragma unroll
    for (int q = 0; q < 4; q++)
        dst[(size_t)(c0 + ty + q * 8) * R + r0 + tx] = rna_tf32(t[tx][ty + q * 8]);
}

// ---------------------------------------------------------------------------
// Fused LayerNorm + mean-pool: zp[b,:] += LN(Q[b,i,:]) / 1024, no Z stored.
// grid (8, BB), block 128 = 4 warps; each warp handles 32 rows.
// ---------------------------------------------------------------------------
__global__ void ln_pool_kernel(const float* __restrict__ Q,
                               const float* __restrict__ g,
                               const float* __restrict__ bta,
                               float* __restrict__ zp)
{
    const int b = blockIdx.y;
    const int chunk = blockIdx.x;
    const int wid = threadIdx.x >> 5;
    const int lane = threadIdx.x & 31;

    float4 g4[4], b4[4];
    #pragma unroll
    for (int q = 0; q < 4; q++) {
        g4[q] = ((const float4*)g)[lane + 32 * q];
        b4[q] = ((const float4*)bta)[lane + 32 * q];
    }
    float4 acc[4];
    #pragma unroll
    for (int q = 0; q < 4; q++) acc[q] = make_float4(0.f, 0.f, 0.f, 0.f);

    const float* base = Q + ((size_t)b * NNODE + chunk * 128 + wid * 32) * DD;
    for (int r = 0; r < 32; r++) {
        const float4* row = (const float4*)(base + (size_t)r * DD);
        float4 v[4];
        float s = 0.f;
        #pragma unroll
        for (int q = 0; q < 4; q++) {
            v[q] = row[lane + 32 * q];
            s += (v[q].x + v[q].y) + (v[q].z + v[q].w);
        }
        #pragma unroll
        for (int o = 16; o; o >>= 1) s += __shfl_xor_sync(0xffffffffu, s, o);
        const float mu = s * (1.f / DD);
        float s2 = 0.f;
        #pragma unroll
        for (int q = 0; q < 4; q++) {
            float dx = v[q].x - mu, dy = v[q].y - mu;
            float dz = v[q].z - mu, dw = v[q].w - mu;
            s2 += (dx * dx + dy * dy) + (dz * dz + dw * dw);
        }
        #pragma unroll
        for (int o = 16; o; o >>= 1) s2 += __shfl_xor_sync(0xffffffffu, s2, o);
        const float rinv = rsqrtf(s2 * (1.f / DD) + 1e-5f);
        #pragma unroll
        for (int q = 0; q < 4; q++) {
            acc[q].x += (v[q].x - mu) * rinv * g4[q].x + b4[q].x;
            acc[q].y += (v[q].y - mu) * rinv * g4[q].y + b4[q].y;
            acc[q].z += (v[q].z - mu) * rinv * g4[q].z + b4[q].z;
            acc[q].w += (v[q].w - mu) * rinv * g4[q].w + b4[q].w;
        }
    }
    const float sc = 1.f / NNODE;
    float* zb = zp + b * DD;
    #pragma unroll
    for (int q = 0; q < 4; q++) {
        int f = 4 * (lane + 32 * q);
        atomicAdd(&zb[f + 0], acc[q].x * sc);
        atomicAdd(&zb[f + 1], acc[q].y * sc);
        atomicAdd(&zb[f + 2], acc[q].z * sc);
        atomicAdd(&zb[f + 3], acc[q].w * sc);
    }
}

// ---------------------------------------------------------------------------
__device__ __forceinline__ float block_sum128(float v, float* red, int t)
{
    #pragma unroll
    for (int off = 16; off; off >>= 1) v += __shfl_down_sync(0xffffffffu, v, off);
    if ((t & 31) == 0) red[t >> 5] = v;
    __syncthreads();
    float s = red[0] + red[1] + red[2] + red[3];
    __syncthreads();
    return s;
}

__global__ void classifier_kernel(const float* __restrict__ zp,
                                  const float* __restrict__ Wc1, const float* __restrict__ bc1,
                                  const float* __restrict__ g1,  const float* __restrict__ t1,
                                  const float* __restrict__ Wc2, const float* __restrict__ bc2,
                                  const float* __restrict__ g2,  const float* __restrict__ t2,
                                  const float* __restrict__ Wc3, const float* __restrict__ bc3,
                                  float* __restrict__ logits)
{
    const int b = blockIdx.x;
    const int t = threadIdx.x;
    __shared__ float z[DD];
    __shared__ float h1[128];
    __shared__ float h2[64];
    __shared__ float red[4];

    #pragma unroll
    for (int i = t; i < DD; i += 128) z[i] = zp[b * DD + i];
    __syncthreads();

    float a1 = bc1[t];
    #pragma unroll 8
    for (int k = 0; k < DD; k++) a1 += z[k] * Wc1[k * 128 + t];
    float mu = block_sum128(a1, red, t) * (1.f / 128.f);
    float d0 = a1 - mu;
    float var = block_sum128(d0 * d0, red, t) * (1.f / 128.f);
    h1[t] = fmaxf(d0 * rsqrtf(var + 1e-5f) * g1[t] + t1[t], 0.f);
    __syncthreads();

    float a2 = 0.f;
    if (t < 64) {
        a2 = bc2[t];
        #pragma unroll 8
        for (int k = 0; k < 128; k++) a2 += h1[k] * Wc2[k * 64 + t];
    }
    float c1 = (t < 64) ? a2 : 0.f;
    float mu2 = block_sum128(c1, red, t) * (1.f / 64.f);
    float d2 = a2 - mu2;
    float c2v = (t < 64) ? d2 * d2 : 0.f;
    float var2 = block_sum128(c2v, red, t) * (1.f / 64.f);
    if (t < 64)
        h2[t] = fmaxf(d2 * rsqrtf(var2 + 1e-5f) * g2[t] + t2[t], 0.f);
    __syncthreads();

    if (t < 4) {
        float a3 = bc3[t];
        #pragma unroll
        for (int k = 0; k < 64; k++) a3 += h2[k] * Wc3[k * 4 + t];
        logits[b * 4 + t] = a3;
    }
}

// ---------------------------------------------------------------------------
extern "C" void kernel_launch(void* const* d_in, const int* in_sizes, int n_in,
                              void* d_out, int out_size)
{
    const float* sc  = (const float*)d_in[0];
    const float* W1  = (const float*)d_in[1];
    const float* b1  = (const float*)d_in[2];
    const float* W2  = (const float*)d_in[3];
    const float* b2  = (const float*)d_in[4];
    const float* lng = (const float*)d_in[5];
    const float* lnb = (const float*)d_in[6];
    const float* Wc1 = (const float*)d_in[7];
    const float* bc1 = (const float*)d_in[8];
    const float* g1  = (const float*)d_in[9];
    const float* t1  = (const float*)d_in[10];
    const float* Wc2 = (const float*)d_in[11];
    const float* bc2 = (const float*)d_in[12];
    const float* g2  = (const float*)d_in[13];
    const float* t2  = (const float*)d_in[14];
    const float* Wc3 = (const float*)d_in[15];
    const float* bc3 = (const float*)d_in[16];
    float* out = (float*)d_out;
    float* zp = out + BB * 4;

    float *At, *P, *Q, *W1t, *W2t, *dis;
    cudaGetSymbolAddress((void**)&At,  g_At);
    cudaGetSymbolAddress((void**)&P,   g_P);
    cudaGetSymbolAddress((void**)&Q,   g_Q);
    cudaGetSymbolAddress((void**)&W1t, g_W1t);
    cudaGetSymbolAddress((void**)&W2t, g_W2t);
    cudaGetSymbolAddress((void**)&dis, g_dis);

    cudaFuncSetAttribute(mma_gemm<false, false, true,  false, true >,
                         cudaFuncAttributeMaxDynamicSharedMemorySize, SMEM_BYTES);
    cudaFuncSetAttribute(mma_gemm<true,  true,  true,  true,  false>,
                         cudaFuncAttributeMaxDynamicSharedMemorySize, SMEM_BYTES);
    cudaFuncSetAttribute(mma_gemm<false, false, true,  false, false>,
                         cudaFuncAttributeMaxDynamicSharedMemorySize, SMEM_BYTES);
    cudaFuncSetAttribute(mma_gemm<true,  false, false, true,  false>,
                         cudaFuncAttributeMaxDynamicSharedMemorySize, SMEM_BYTES);

    // zero zp (output region) + dis accumulator — every replay, in-graph
    zero2_kernel<<<128, 256>>>(zp, BB * DD, dis, BB * NNODE);

    // At = rna(sc^T) fused with degree column-sums; then rsqrt
    dim3 tb(32, 8);
    transpose_rna_cs<<<dim3(NNODE / 32, NNODE / 32, BB), tb>>>(sc, At, dis);
    rsqrt_fin<<<BB * NNODE / 256, 256>>>(dis);

    transpose_rna_w<<<dim3(DD / 32, NNODE / 32), tb>>>(W1, W1t, NNODE, DD);
    transpose_rna_w<<<dim3(DD / 32, DD / 32), tb>>>(W2, W2t, DD, DD);

    // G1: P[(b,j),n] = rna(dis[b,j]*(sc@W1)[b,j,n])  (A=sc raw, rna in-register)
    mma_gemm<false, false, true, false, true><<<dim3(4, 256, 1), 256, SMEM_BYTES>>>(
        sc, W1t, P, dis, nullptr, NNODE, NNODE, NNODE, DD, 0, 0, 0, 0);

    // G2: Q[(b,i),n] = rna(relu(dis[b,i]*(At@P) + b1))
    mma_gemm<true, true, true, true, false><<<dim3(4, 8, BB), 256, SMEM_BYTES>>>(
        At, P, Q, dis, b1, NNODE, NNODE, DD, DD,
        (size_t)NNODE * NNODE, (size_t)NNODE * DD, (size_t)NNODE * DD, NNODE);

    // G3: P[(b,j),n] = rna(dis[b,j]*(Q@W2))
    mma_gemm<false, false, true, false, false><<<dim3(4, 256, 1), 256, SMEM_BYTES>>>(
        Q, W2t, P, dis, nullptr, DD, DD, DD, DD, 0, 0, 0, 0);

    // G4: Q[(b,i),n] = dis[b,i]*(At@P) + b2   (fp32 out)
    mma_gemm<true, false, false, true, false><<<dim3(4, 8, BB), 256, SMEM_BYTES>>>(
        At, P, Q, dis, b2, NNODE, NNODE, DD, DD,
        (size_t)NNODE * NNODE, (size_t)NNODE * DD, (size_t)NNODE * DD, NNODE);

    // fused LN + mean-pool -> zp (no Z materialization)
    ln_pool_kernel<<<dim3(8, BB), 128>>>(Q, lng, lnb, zp);

    // classifier -> out[0:128)
    classifier_kernel<<<BB, 128>>>(zp, Wc1, bc1, g1, t1,
                                   Wc2, bc2, g2, t2, Wc3, bc3, out);
}

// round 9
// speedup vs baseline: 1.5593x; 1.5593x over previous
#include <cuda_runtime.h>
#include <cuda_fp16.h>
#include <cstdint>
#include <cstddef>

#define BB 32
#define NNODE 1024
#define DD 512

__device__ __half g_sch[(size_t)BB * NNODE * NNODE];   // fp16 sc
__device__ __half g_Ath[(size_t)BB * NNODE * NNODE];   // fp16 sc^T
__device__ __half g_P  [(size_t)BB * NNODE * DD];      // Y1t / Y2t (feat-major fp16)
__device__ __half g_Qh [(size_t)BB * NNODE * DD];      // H1 (fp16)
__device__ float  g_Q32[(size_t)BB * NNODE * DD];      // H2 (fp32)
__device__ __half g_W1t[DD * NNODE];
__device__ __half g_W2t[DD * DD];
__device__ float  g_dis[BB * NNODE];

__device__ __forceinline__ uint32_t smem_u32(const void* p) {
    uint32_t a;
    asm("{ .reg .u64 t; cvta.to.shared.u64 t, %1; cvt.u32.u64 %0, t; }" : "=r"(a) : "l"(p));
    return a;
}
__device__ __forceinline__ void cp16(uint32_t s, const void* g) {
    asm volatile("cp.async.cg.shared.global [%0], [%1], 16;" :: "r"(s), "l"(g));
}
__device__ __forceinline__ uint32_t lds32(uint32_t a) {
    uint32_t v; asm volatile("ld.shared.b32 %0, [%1];" : "=r"(v) : "r"(a)); return v;
}

// fp16 tile geometry: rows of 32 fp16 (64B) padded to 40 fp16 (80B = 20 banks).
static constexpr int ROW_B   = 80;                  // bytes per smem row
static constexpr int ATILE   = 128 * ROW_B;         // 10240 B
static constexpr int STG     = 2 * ATILE;           // 20480 B per stage
static constexpr int SMEM_BYTES = 2 * STG;          // 40960 B (< 48KB default)
static constexpr int T_PITCH = 144;                 // fp16 pitch for transpose staging

// ---------------------------------------------------------------------------
// fp16 mma.sync GEMM: CTA tile 128x128, K-chunk 32 (2 x k16), 8 warps (2x4),
// warp tile 64x32. A [M][K] row-major fp16, B [N][K] row-major fp16.
// C[m,n] = acc*dis[m] (+bias) (relu); output fp16 (OUTHALF) or fp32.
// TOUT: write transposed out[b][n][j] fp16 via SMEM staging (grid.z==1, b=m0>>10).
// ---------------------------------------------------------------------------
template<bool TOUT, bool RELU, bool HASBIAS, bool OUTHALF>
__global__ __launch_bounds__(256, 2)
void hgemm(const __half* __restrict__ Ap, const __half* __restrict__ Bp,
           void* __restrict__ Cpv, const float* __restrict__ disv,
           const float* __restrict__ bias,
           int K, int lda, int ldb, int ldc,
           size_t sA, size_t sB, size_t sC, size_t sD)
{
    extern __shared__ char smem[];
    const uint32_t sbase = smem_u32(smem);
    const int tid = threadIdx.x;
    const int wid = tid >> 5;
    const int lane = tid & 31;
    const int wm = wid >> 2;
    const int wn = wid & 3;
    const int lrow = lane >> 2;
    const int lcol = lane & 3;
    const int bz = blockIdx.z;
    const int m0 = blockIdx.y * 128;
    const int n0 = blockIdx.x * 128;

    Ap += (size_t)bz * sA;
    Bp += (size_t)bz * sB;
    disv += (size_t)bz * sD;
    // *** batch offset on output (was missing in R8 — the rel_err=1.0 bug) ***
    if (OUTHALF || TOUT) Cpv = (void*)((__half*)Cpv + (size_t)bz * sC);
    else                 Cpv = (void*)((float*)Cpv + (size_t)bz * sC);

    const int S = K / 32;

    auto load_stage = [&](int k0, uint32_t soff) {
        #pragma unroll
        for (int p = 0; p < 2; p++) {
            int id = tid + 256 * p;
            int row = id >> 2, c = id & 3;
            cp16(sbase + soff + (uint32_t)(row * ROW_B + c * 16),
                 Ap + (size_t)(m0 + row) * lda + k0 + c * 8);
            cp16(sbase + soff + ATILE + (uint32_t)(row * ROW_B + c * 16),
                 Bp + (size_t)(n0 + row) * ldb + k0 + c * 8);
        }
        asm volatile("cp.async.commit_group;" ::: "memory");
    };

    load_stage(0, 0);
    if (S > 1) load_stage(32, STG);

    float acc[4][4][4];
    #pragma unroll
    for (int mi = 0; mi < 4; mi++)
        #pragma unroll
        for (int ni = 0; ni < 4; ni++)
            #pragma unroll
            for (int q = 0; q < 4; q++) acc[mi][ni][q] = 0.f;

    for (int s = 0; s < S; s++) {
        if (s + 1 < S) asm volatile("cp.async.wait_group 1;" ::: "memory");
        else           asm volatile("cp.async.wait_group 0;" ::: "memory");
        __syncthreads();

        const uint32_t aB = sbase + (uint32_t)(s & 1) * STG;
        const uint32_t bB = aB + ATILE;

        #pragma unroll
        for (int kk = 0; kk < 2; kk++) {
            uint32_t a[4][4];
            #pragma unroll
            for (int mi = 0; mi < 4; mi++) {
                uint32_t ad = aB + (uint32_t)((wm * 64 + mi * 16 + lrow) * ROW_B
                                              + kk * 32 + lcol * 4);
                a[mi][0] = lds32(ad);
                a[mi][1] = lds32(ad + 8 * ROW_B);
                a[mi][2] = lds32(ad + 16);
                a[mi][3] = lds32(ad + 8 * ROW_B + 16);
            }
            #pragma unroll
            for (int ni = 0; ni < 4; ni++) {
                uint32_t bd = bB + (uint32_t)((wn * 32 + ni * 8 + lrow) * ROW_B
                                              + kk * 32 + lcol * 4);
                uint32_t b0 = lds32(bd);
                uint32_t b1 = lds32(bd + 16);
                #pragma unroll
                for (int mi = 0; mi < 4; mi++) {
                    asm volatile(
                        "mma.sync.aligned.m16n8k16.row.col.f32.f16.f16.f32 "
                        "{%0,%1,%2,%3}, {%4,%5,%6,%7}, {%8,%9}, {%0,%1,%2,%3};"
                        : "+f"(acc[mi][ni][0]), "+f"(acc[mi][ni][1]),
                          "+f"(acc[mi][ni][2]), "+f"(acc[mi][ni][3])
                        : "r"(a[mi][0]), "r"(a[mi][1]), "r"(a[mi][2]), "r"(a[mi][3]),
                          "r"(b0), "r"(b1));
                }
            }
        }
        __syncthreads();
        if (s + 2 < S) load_stage((s + 2) * 32, (uint32_t)(s & 1) * STG);
    }

    if (TOUT) {
        // stage transposed fp16 tile [n_loc][m_loc], then coalesced write
        __half* sb = (__half*)smem;
        #pragma unroll
        for (int mi = 0; mi < 4; mi++) {
            const int mloc = wm * 64 + mi * 16 + lrow;
            const float d0 = disv[m0 + mloc];
            const float d1 = disv[m0 + mloc + 8];
            #pragma unroll
            for (int ni = 0; ni < 4; ni++) {
                const int nloc = wn * 32 + ni * 8 + 2 * lcol;
                sb[nloc * T_PITCH + mloc]           = __float2half_rn(acc[mi][ni][0] * d0);
                sb[(nloc + 1) * T_PITCH + mloc]     = __float2half_rn(acc[mi][ni][1] * d0);
                sb[nloc * T_PITCH + mloc + 8]       = __float2half_rn(acc[mi][ni][2] * d1);
                sb[(nloc + 1) * T_PITCH + mloc + 8] = __float2half_rn(acc[mi][ni][3] * d1);
            }
        }
        __syncthreads();
        const int b = m0 >> 10;
        const int j0 = m0 & 1023;
        __half* outB = (__half*)Cpv + (size_t)b * DD * 1024 + j0;
        #pragma unroll
        for (int p = 0; p < 8; p++) {
            int id = tid + 256 * p;
            int row = id >> 4, c = id & 15;
            *(uint4*)(outB + (size_t)(n0 + row) * 1024 + c * 8) =
                *(const uint4*)(sb + row * T_PITCH + c * 8);
        }
    } else {
        #pragma unroll
        for (int mi = 0; mi < 4; mi++) {
            const int ml = m0 + wm * 64 + mi * 16 + lrow;
            const float d0 = disv[ml];
            const float d1 = disv[ml + 8];
            #pragma unroll
            for (int ni = 0; ni < 4; ni++) {
                const int n = n0 + wn * 32 + ni * 8 + 2 * lcol;
                float bx = 0.f, by = 0.f;
                if (HASBIAS) { bx = bias[n]; by = bias[n + 1]; }
                float v0 = acc[mi][ni][0] * d0 + bx;
                float v1 = acc[mi][ni][1] * d0 + by;
                float v2 = acc[mi][ni][2] * d1 + bx;
                float v3 = acc[mi][ni][3] * d1 + by;
                if (RELU) {
                    v0 = fmaxf(v0, 0.f); v1 = fmaxf(v1, 0.f);
                    v2 = fmaxf(v2, 0.f); v3 = fmaxf(v3, 0.f);
                }
                if (OUTHALF) {
                    __half* C = (__half*)Cpv;
                    *(__half2*)&C[(size_t)ml * ldc + n] = __floats2half2_rn(v0, v1);
                    *(__half2*)&C[(size_t)(ml + 8) * ldc + n] = __floats2half2_rn(v2, v3);
                } else {
                    float* C = (float*)Cpv;
                    *(float2*)&C[(size_t)ml * ldc + n] = make_float2(v0, v1);
                    *(float2*)&C[(size_t)(ml + 8) * ldc + n] = make_float2(v2, v3);
                }
            }
        }
    }
}

// ---------------------------------------------------------------------------
__global__ void zero2_kernel(float* a, int na, float* c, int nc)
{
    int i = blockIdx.x * 256 + threadIdx.x;
    if (i < na) a[i] = 0.f;
    if (i < nc) c[i] = 0.f;
}

// one pass over sc: fp16 copy + fp16 transpose + degree column sums
__global__ void sc_prep(const float* __restrict__ sc, __half* __restrict__ sch,
                        __half* __restrict__ Ath, float* __restrict__ dacc)
{
    __shared__ float t[32][33];
    __shared__ float cs[32];
    const size_t zoff = (size_t)blockIdx.z * NNODE * NNODE;
    const int r0 = blockIdx.y * 32, c0 = blockIdx.x * 32;
    const int tx = threadIdx.x, ty = threadIdx.y;
    float v[4];
    #pragma unroll
    for (int q = 0; q < 4; q++) {
        size_t idx = zoff + (size_t)(r0 + ty + q * 8) * NNODE + c0 + tx;
        v[q] = sc[idx];
        sch[idx] = __float2half_rn(v[q]);
        t[ty + q * 8][tx] = v[q];
    }
    if (ty == 0) cs[tx] = 0.f;
    __syncthreads();
    atomicAdd(&cs[tx], (v[0] + v[1]) + (v[2] + v[3]));
    #pragma unroll
    for (int q = 0; q < 4; q++)
        Ath[zoff + (size_t)(c0 + ty + q * 8) * NNODE + r0 + tx] =
            __float2half_rn(t[tx][ty + q * 8]);
    __syncthreads();
    if (ty == 0) atomicAdd(&dacc[(size_t)blockIdx.z * NNODE + c0 + tx], cs[tx]);
}

__global__ void rsqrt_fin(float* __restrict__ dis)
{
    int i = blockIdx.x * 256 + threadIdx.x;
    float s = dis[i];
    dis[i] = (s > 0.f) ? rsqrtf(s) : 0.f;
}

// weight transpose: src fp32 [R][C] -> dst fp16 [C][R]
__global__ void w_prep(const float* __restrict__ src, __half* __restrict__ dst,
                       int R, int C)
{
    __shared__ float t[32][33];
    const int r0 = blockIdx.y * 32, c0 = blockIdx.x * 32;
    const int tx = threadIdx.x, ty = threadIdx.y;
    #pragma unroll
    for (int q = 0; q < 4; q++)
        t[ty + q * 8][tx] = src[(size_t)(r0 + ty + q * 8) * C + c0 + tx];
    __syncthreads();
    #pragma unroll
    for (int q = 0; q < 4; q++)
        dst[(size_t)(c0 + ty + q * 8) * R + r0 + tx] = __float2half_rn(t[tx][ty + q * 8]);
}

// ---------------------------------------------------------------------------
// Fused LayerNorm + mean-pool: zp[b,:] += LN(Q[b,i,:]) / 1024
// ---------------------------------------------------------------------------
__global__ void ln_pool_kernel(const float* __restrict__ Q,
                               const float* __restrict__ g,
                               const float* __restrict__ bta,
                               float* __restrict__ zp)
{
    const int b = blockIdx.y;
    const int chunk = blockIdx.x;
    const int wid = threadIdx.x >> 5;
    const int lane = threadIdx.x & 31;

    float4 g4[4], b4[4];
    #pragma unroll
    for (int q = 0; q < 4; q++) {
        g4[q] = ((const float4*)g)[lane + 32 * q];
        b4[q] = ((const float4*)bta)[lane + 32 * q];
    }
    float4 acc[4];
    #pragma unroll
    for (int q = 0; q < 4; q++) acc[q] = make_float4(0.f, 0.f, 0.f, 0.f);

    const float* base = Q + ((size_t)b * NNODE + chunk * 128 + wid * 32) * DD;
    for (int r = 0; r < 32; r++) {
        const float4* row = (const float4*)(base + (size_t)r * DD);
        float4 v[4];
        float s = 0.f;
        #pragma unroll
        for (int q = 0; q < 4; q++) {
            v[q] = row[lane + 32 * q];
            s += (v[q].x + v[q].y) + (v[q].z + v[q].w);
        }
        #pragma unroll
        for (int o = 16; o; o >>= 1) s += __shfl_xor_sync(0xffffffffu, s, o);
        const float mu = s * (1.f / DD);
        float s2 = 0.f;
        #pragma unroll
        for (int q = 0; q < 4; q++) {
            float dx = v[q].x - mu, dy = v[q].y - mu;
            float dz = v[q].z - mu, dw = v[q].w - mu;
            s2 += (dx * dx + dy * dy) + (dz * dz + dw * dw);
        }
        #pragma unroll
        for (int o = 16; o; o >>= 1) s2 += __shfl_xor_sync(0xffffffffu, s2, o);
        const float rinv = rsqrtf(s2 * (1.f / DD) + 1e-5f);
        #pragma unroll
        for (int q = 0; q < 4; q++) {
            acc[q].x += (v[q].x - mu) * rinv * g4[q].x + b4[q].x;
            acc[q].y += (v[q].y - mu) * rinv * g4[q].y + b4[q].y;
            acc[q].z += (v[q].z - mu) * rinv * g4[q].z + b4[q].z;
            acc[q].w += (v[q].w - mu) * rinv * g4[q].w + b4[q].w;
        }
    }
    const float sc = 1.f / NNODE;
    float* zb = zp + b * DD;
    #pragma unroll
    for (int q = 0; q < 4; q++) {
        int f = 4 * (lane + 32 * q);
        atomicAdd(&zb[f + 0], acc[q].x * sc);
        atomicAdd(&zb[f + 1], acc[q].y * sc);
        atomicAdd(&zb[f + 2], acc[q].z * sc);
        atomicAdd(&zb[f + 3], acc[q].w * sc);
    }
}

// ---------------------------------------------------------------------------
__device__ __forceinline__ float block_sum128(float v, float* red, int t)
{
    #pragma unroll
    for (int off = 16; off; off >>= 1) v += __shfl_down_sync(0xffffffffu, v, off);
    if ((t & 31) == 0) red[t >> 5] = v;
    __syncthreads();
    float s = red[0] + red[1] + red[2] + red[3];
    __syncthreads();
    return s;
}

__global__ void classifier_kernel(const float* __restrict__ zp,
                                  const float* __restrict__ Wc1, const float* __restrict__ bc1,
                                  const float* __restrict__ g1,  const float* __restrict__ t1,
                                  const float* __restrict__ Wc2, const float* __restrict__ bc2,
                                  const float* __restrict__ g2,  const float* __restrict__ t2,
                                  const float* __restrict__ Wc3, const float* __restrict__ bc3,
                                  float* __restrict__ logits)
{
    const int b = blockIdx.x;
    const int t = threadIdx.x;
    __shared__ float z[DD];
    __shared__ float h1[128];
    __shared__ float h2[64];
    __shared__ float red[4];

    #pragma unroll
    for (int i = t; i < DD; i += 128) z[i] = zp[b * DD + i];
    __syncthreads();

    float a1 = bc1[t];
    #pragma unroll 8
    for (int k = 0; k < DD; k++) a1 += z[k] * Wc1[k * 128 + t];
    float mu = block_sum128(a1, red, t) * (1.f / 128.f);
    float d0 = a1 - mu;
    float var = block_sum128(d0 * d0, red, t) * (1.f / 128.f);
    h1[t] = fmaxf(d0 * rsqrtf(var + 1e-5f) * g1[t] + t1[t], 0.f);
    __syncthreads();

    float a2 = 0.f;
    if (t < 64) {
        a2 = bc2[t];
        #pragma unroll 8
        for (int k = 0; k < 128; k++) a2 += h1[k] * Wc2[k * 64 + t];
    }
    float c1 = (t < 64) ? a2 : 0.f;
    float mu2 = block_sum128(c1, red, t) * (1.f / 64.f);
    float d2 = a2 - mu2;
    float c2v = (t < 64) ? d2 * d2 : 0.f;
    float var2 = block_sum128(c2v, red, t) * (1.f / 64.f);
    if (t < 64)
        h2[t] = fmaxf(d2 * rsqrtf(var2 + 1e-5f) * g2[t] + t2[t], 0.f);
    __syncthreads();

    if (t < 4) {
        float a3 = bc3[t];
        #pragma unroll
        for (int k = 0; k < 64; k++) a3 += h2[k] * Wc3[k * 4 + t];
        logits[b * 4 + t] = a3;
    }
}

// ---------------------------------------------------------------------------
extern "C" void kernel_launch(void* const* d_in, const int* in_sizes, int n_in,
                              void* d_out, int out_size)
{
    const float* sc  = (const float*)d_in[0];
    const float* W1  = (const float*)d_in[1];
    const float* b1  = (const float*)d_in[2];
    const float* W2  = (const float*)d_in[3];
    const float* b2  = (const float*)d_in[4];
    const float* lng = (const float*)d_in[5];
    const float* lnb = (const float*)d_in[6];
    const float* Wc1 = (const float*)d_in[7];
    const float* bc1 = (const float*)d_in[8];
    const float* g1  = (const float*)d_in[9];
    const float* t1  = (const float*)d_in[10];
    const float* Wc2 = (const float*)d_in[11];
    const float* bc2 = (const float*)d_in[12];
    const float* g2  = (const float*)d_in[13];
    const float* t2  = (const float*)d_in[14];
    const float* Wc3 = (const float*)d_in[15];
    const float* bc3 = (const float*)d_in[16];
    float* out = (float*)d_out;
    float* zp = out + BB * 4;

    __half *sch, *Ath, *P, *Qh, *W1t, *W2t;
    float *Q32, *dis;
    cudaGetSymbolAddress((void**)&sch, g_sch);
    cudaGetSymbolAddress((void**)&Ath, g_Ath);
    cudaGetSymbolAddress((void**)&P,   g_P);
    cudaGetSymbolAddress((void**)&Qh,  g_Qh);
    cudaGetSymbolAddress((void**)&Q32, g_Q32);
    cudaGetSymbolAddress((void**)&W1t, g_W1t);
    cudaGetSymbolAddress((void**)&W2t, g_W2t);
    cudaGetSymbolAddress((void**)&dis, g_dis);

    // zero zp (output region) + dis accumulator — every replay, in-graph
    zero2_kernel<<<128, 256>>>(zp, BB * DD, dis, BB * NNODE);

    dim3 tb(32, 8);
    sc_prep<<<dim3(32, 32, BB), tb>>>(sc, sch, Ath, dis);
    rsqrt_fin<<<BB * NNODE / 256, 256>>>(dis);
    w_prep<<<dim3(DD / 32, NNODE / 32), tb>>>(W1, W1t, NNODE, DD);
    w_prep<<<dim3(DD / 32, DD / 32), tb>>>(W2, W2t, DD, DD);

    // G1: P[b][n][j] = h(dis[b,j] * (sc@W1)[b,j,n])      (TOUT)
    hgemm<true, false, false, true><<<dim3(4, 256, 1), 256, SMEM_BYTES>>>(
        sch, W1t, P, dis, nullptr, NNODE, NNODE, NNODE, 0, 0, 0, 0, 0);

    // G2: Qh[b][i][n] = h(relu(dis[b,i]*(At@P^T) + b1))
    hgemm<false, true, true, true><<<dim3(4, 8, BB), 256, SMEM_BYTES>>>(
        Ath, P, Qh, dis, b1, NNODE, NNODE, NNODE, DD,
        (size_t)NNODE * NNODE, (size_t)DD * NNODE, (size_t)NNODE * DD, NNODE);

    // G3: P[b][n][j] = h(dis[b,j] * (Qh@W2)[b,j,n])      (TOUT)
    hgemm<true, false, false, true><<<dim3(4, 256, 1), 256, SMEM_BYTES>>>(
        Qh, W2t, P, dis, nullptr, DD, DD, DD, 0, 0, 0, 0, 0);

    // G4: Q32[b][i][n] = dis[b,i]*(At@P^T) + b2  (fp32)
    hgemm<false, false, true, false><<<dim3(4, 8, BB), 256, SMEM_BYTES>>>(
        Ath, P, Q32, dis, b2, NNODE, NNODE, NNODE, DD,
        (size_t)NNODE * NNODE, (size_t)DD * NNODE, (size_t)NNODE * DD, NNODE);

    // fused LN + mean-pool -> zp, then classifier -> out[0:128)
    ln_pool_kernel<<<dim3(8, BB), 128>>>(Q32, lng, lnb, zp);
    classifier_kernel<<<BB, 128>>>(zp, Wc1, bc1, g1, t1,
                                   Wc2, bc2, g2, t2, Wc3, bc3, out);
}

// round 10
// speedup vs baseline: 1.5950x; 1.0229x over previous
#include <cuda_runtime.h>
#include <cuda_fp16.h>
#include <cstdint>
#include <cstddef>

#define BB 32
#define NNODE 1024
#define DD 512

__device__ __half g_sch[(size_t)BB * NNODE * NNODE];   // fp16 sc
__device__ __half g_Ath[(size_t)BB * NNODE * NNODE];   // fp16 sc^T
__device__ __half g_P  [(size_t)BB * NNODE * DD];      // Y1t / Y2t (feat-major fp16)
__device__ __half g_Qh [(size_t)BB * NNODE * DD];      // H1 (fp16)
__device__ float  g_Q32[(size_t)BB * NNODE * DD];      // H2 (fp32)
__device__ __half g_W1t[DD * NNODE];
__device__ __half g_W2t[DD * DD];
__device__ float  g_dis[BB * NNODE];

__device__ __forceinline__ uint32_t smem_u32(const void* p) {
    uint32_t a;
    asm("{ .reg .u64 t; cvta.to.shared.u64 t, %1; cvt.u32.u64 %0, t; }" : "=r"(a) : "l"(p));
    return a;
}
__device__ __forceinline__ void cp16(uint32_t s, const void* g) {
    asm volatile("cp.async.cg.shared.global [%0], [%1], 16;" :: "r"(s), "l"(g));
}
__device__ __forceinline__ void ldm_x4(uint32_t* r, uint32_t a) {
    asm volatile("ldmatrix.sync.aligned.m8n8.x4.shared.b16 {%0,%1,%2,%3}, [%4];"
        : "=r"(r[0]), "=r"(r[1]), "=r"(r[2]), "=r"(r[3]) : "r"(a));
}
__device__ __forceinline__ void ldm_x2(uint32_t& r0, uint32_t& r1, uint32_t a) {
    asm volatile("ldmatrix.sync.aligned.m8n8.x2.shared.b16 {%0,%1}, [%2];"
        : "=r"(r0), "=r"(r1) : "r"(a));
}

// fp16 tile geometry: rows of 32 fp16 (64B) padded to 40 fp16 (80B = 20 banks).
// 80B pitch -> ldmatrix 8-row phases are conflict-free (banks {0,20,8,28,16,4,24,12}+[0,3]).
static constexpr int ROW_B   = 80;                  // bytes per smem row
static constexpr int ATILE   = 128 * ROW_B;         // 10240 B
static constexpr int STG     = 2 * ATILE;           // 20480 B per stage
static constexpr int SMEM_BYTES = 2 * STG;          // 40960 B (< 48KB default)
static constexpr int T_PITCH = 144;                 // fp16 pitch for transpose staging

// ---------------------------------------------------------------------------
// fp16 mma.sync GEMM: CTA tile 128x128, K-chunk 32 (2 x k16), 8 warps (2x4),
// warp tile 64x32, ldmatrix fragment loads.
// ---------------------------------------------------------------------------
template<bool TOUT, bool RELU, bool HASBIAS, bool OUTHALF>
__global__ __launch_bounds__(256, 2)
void hgemm(const __half* __restrict__ Ap, const __half* __restrict__ Bp,
           void* __restrict__ Cpv, const float* __restrict__ disv,
           const float* __restrict__ bias,
           int K, int lda, int ldb, int ldc,
           size_t sA, size_t sB, size_t sC, size_t sD)
{
    extern __shared__ char smem[];
    const uint32_t sbase = smem_u32(smem);
    const int tid = threadIdx.x;
    const int wid = tid >> 5;
    const int lane = tid & 31;
    const int wm = wid >> 2;
    const int wn = wid & 3;
    const int lrow = lane >> 2;
    const int lcol = lane & 3;
    const int bz = blockIdx.z;
    const int m0 = blockIdx.y * 128;
    const int n0 = blockIdx.x * 128;

    Ap += (size_t)bz * sA;
    Bp += (size_t)bz * sB;
    disv += (size_t)bz * sD;
    if (OUTHALF || TOUT) Cpv = (void*)((__half*)Cpv + (size_t)bz * sC);
    else                 Cpv = (void*)((float*)Cpv + (size_t)bz * sC);

    const int S = K / 32;

    auto load_stage = [&](int k0, uint32_t soff) {
        #pragma unroll
        for (int p = 0; p < 2; p++) {
            int id = tid + 256 * p;
            int row = id >> 2, c = id & 3;
            cp16(sbase + soff + (uint32_t)(row * ROW_B + c * 16),
                 Ap + (size_t)(m0 + row) * lda + k0 + c * 8);
            cp16(sbase + soff + ATILE + (uint32_t)(row * ROW_B + c * 16),
                 Bp + (size_t)(n0 + row) * ldb + k0 + c * 8);
        }
        asm volatile("cp.async.commit_group;" ::: "memory");
    };

    load_stage(0, 0);
    if (S > 1) load_stage(32, STG);

    float acc[4][4][4];
    #pragma unroll
    for (int mi = 0; mi < 4; mi++)
        #pragma unroll
        for (int ni = 0; ni < 4; ni++)
            #pragma unroll
            for (int q = 0; q < 4; q++) acc[mi][ni][q] = 0.f;

    // ldmatrix per-lane address components
    const uint32_t aRowBase = (uint32_t)(wm * 64 + (lane & 15)) * ROW_B
                              + ((uint32_t)(lane >> 4) & 1u) * 16u;
    const uint32_t bRowBase = (uint32_t)(wn * 32 + (lane & 7)) * ROW_B
                              + ((uint32_t)(lane >> 3) & 1u) * 16u;

    for (int s = 0; s < S; s++) {
        if (s + 1 < S) asm volatile("cp.async.wait_group 1;" ::: "memory");
        else           asm volatile("cp.async.wait_group 0;" ::: "memory");
        __syncthreads();

        const uint32_t aB = sbase + (uint32_t)(s & 1) * STG;
        const uint32_t bB = aB + ATILE;

        #pragma unroll
        for (int kk = 0; kk < 2; kk++) {
            uint32_t a[4][4];
            #pragma unroll
            for (int mi = 0; mi < 4; mi++)
                ldm_x4(a[mi], aB + aRowBase + (uint32_t)(mi * 16) * ROW_B + kk * 32);
            #pragma unroll
            for (int ni = 0; ni < 4; ni++) {
                uint32_t b0, b1;
                ldm_x2(b0, b1, bB + bRowBase + (uint32_t)(ni * 8) * ROW_B + kk * 32);
                #pragma unroll
                for (int mi = 0; mi < 4; mi++) {
                    asm volatile(
                        "mma.sync.aligned.m16n8k16.row.col.f32.f16.f16.f32 "
                        "{%0,%1,%2,%3}, {%4,%5,%6,%7}, {%8,%9}, {%0,%1,%2,%3};"
                        : "+f"(acc[mi][ni][0]), "+f"(acc[mi][ni][1]),
                          "+f"(acc[mi][ni][2]), "+f"(acc[mi][ni][3])
                        : "r"(a[mi][0]), "r"(a[mi][1]), "r"(a[mi][2]), "r"(a[mi][3]),
                          "r"(b0), "r"(b1));
                }
            }
        }
        __syncthreads();
        if (s + 2 < S) load_stage((s + 2) * 32, (uint32_t)(s & 1) * STG);
    }

    if (TOUT) {
        __half* sb = (__half*)smem;
        #pragma unroll
        for (int mi = 0; mi < 4; mi++) {
            const int mloc = wm * 64 + mi * 16 + lrow;
            const float d0 = disv[m0 + mloc];
            const float d1 = disv[m0 + mloc + 8];
            #pragma unroll
            for (int ni = 0; ni < 4; ni++) {
                const int nloc = wn * 32 + ni * 8 + 2 * lcol;
                sb[nloc * T_PITCH + mloc]           = __float2half_rn(acc[mi][ni][0] * d0);
                sb[(nloc + 1) * T_PITCH + mloc]     = __float2half_rn(acc[mi][ni][1] * d0);
                sb[nloc * T_PITCH + mloc + 8]       = __float2half_rn(acc[mi][ni][2] * d1);
                sb[(nloc + 1) * T_PITCH + mloc + 8] = __float2half_rn(acc[mi][ni][3] * d1);
            }
        }
        __syncthreads();
        const int b = m0 >> 10;
        const int j0 = m0 & 1023;
        __half* outB = (__half*)Cpv + (size_t)b * DD * 1024 + j0;
        #pragma unroll
        for (int p = 0; p < 8; p++) {
            int id = tid + 256 * p;
            int row = id >> 4, c = id & 15;
            *(uint4*)(outB + (size_t)(n0 + row) * 1024 + c * 8) =
                *(const uint4*)(sb + row * T_PITCH + c * 8);
        }
    } else {
        #pragma unroll
        for (int mi = 0; mi < 4; mi++) {
            const int ml = m0 + wm * 64 + mi * 16 + lrow;
            const float d0 = disv[ml];
            const float d1 = disv[ml + 8];
            #pragma unroll
            for (int ni = 0; ni < 4; ni++) {
                const int n = n0 + wn * 32 + ni * 8 + 2 * lcol;
                float bx = 0.f, by = 0.f;
                if (HASBIAS) { bx = bias[n]; by = bias[n + 1]; }
                float v0 = acc[mi][ni][0] * d0 + bx;
                float v1 = acc[mi][ni][1] * d0 + by;
                float v2 = acc[mi][ni][2] * d1 + bx;
                float v3 = acc[mi][ni][3] * d1 + by;
                if (RELU) {
                    v0 = fmaxf(v0, 0.f); v1 = fmaxf(v1, 0.f);
                    v2 = fmaxf(v2, 0.f); v3 = fmaxf(v3, 0.f);
                }
                if (OUTHALF) {
                    __half* C = (__half*)Cpv;
                    *(__half2*)&C[(size_t)ml * ldc + n] = __floats2half2_rn(v0, v1);
                    *(__half2*)&C[(size_t)(ml + 8) * ldc + n] = __floats2half2_rn(v2, v3);
                } else {
                    float* C = (float*)Cpv;
                    *(float2*)&C[(size_t)ml * ldc + n] = make_float2(v0, v1);
                    *(float2*)&C[(size_t)(ml + 8) * ldc + n] = make_float2(v2, v3);
                }
            }
        }
    }
}

// ---------------------------------------------------------------------------
__global__ void zero2_kernel(float* a, int na, float* c, int nc)
{
    int i = blockIdx.x * 256 + threadIdx.x;
    if (i < na) a[i] = 0.f;
    if (i < nc) c[i] = 0.f;
}

__global__ void sc_prep(const float* __restrict__ sc, __half* __restrict__ sch,
                        __half* __restrict__ Ath, float* __restrict__ dacc)
{
    __shared__ float t[32][33];
    __shared__ float cs[32];
    const size_t zoff = (size_t)blockIdx.z * NNODE * NNODE;
    const int r0 = blockIdx.y * 32, c0 = blockIdx.x * 32;
    const int tx = threadIdx.x, ty = threadIdx.y;
    float v[4];
    #pragma unroll
    for (int q = 0; q < 4; q++) {
        size_t idx = zoff + (size_t)(r0 + ty + q * 8) * NNODE + c0 + tx;
        v[q] = sc[idx];
        sch[idx] = __float2half_rn(v[q]);
        t[ty + q * 8][tx] = v[q];
    }
    if (ty == 0) cs[tx] = 0.f;
    __syncthreads();
    atomicAdd(&cs[tx], (v[0] + v[1]) + (v[2] + v[3]));
    #pragma unroll
    for (int q = 0; q < 4; q++)
        Ath[zoff + (size_t)(c0 + ty + q * 8) * NNODE + r0 + tx] =
            __float2half_rn(t[tx][ty + q * 8]);
    __syncthreads();
    if (ty == 0) atomicAdd(&dacc[(size_t)blockIdx.z * NNODE + c0 + tx], cs[tx]);
}

__global__ void rsqrt_fin(float* __restrict__ dis)
{
    int i = blockIdx.x * 256 + threadIdx.x;
    float s = dis[i];
    dis[i] = (s > 0.f) ? rsqrtf(s) : 0.f;
}

__global__ void w_prep(const float* __restrict__ src, __half* __restrict__ dst,
                       int R, int C)
{
    __shared__ float t[32][33];
    const int r0 = blockIdx.y * 32, c0 = blockIdx.x * 32;
    const int tx = threadIdx.x, ty = threadIdx.y;
    #pragma unroll
    for (int q = 0; q < 4; q++)
        t[ty + q * 8][tx] = src[(size_t)(r0 + ty + q * 8) * C + c0 + tx];
    __syncthreads();
    #pragma unroll
    for (int q = 0; q < 4; q++)
        dst[(size_t)(c0 + ty + q * 8) * R + r0 + tx] = __float2half_rn(t[tx][ty + q * 8]);
}

// ---------------------------------------------------------------------------
__global__ void ln_pool_kernel(const float* __restrict__ Q,
                               const float* __restrict__ g,
                               const float* __restrict__ bta,
                               float* __restrict__ zp)
{
    const int b = blockIdx.y;
    const int chunk = blockIdx.x;
    const int wid = threadIdx.x >> 5;
    const int lane = threadIdx.x & 31;

    float4 g4[4], b4[4];
    #pragma unroll
    for (int q = 0; q < 4; q++) {
        g4[q] = ((const float4*)g)[lane + 32 * q];
        b4[q] = ((const float4*)bta)[lane + 32 * q];
    }
    float4 acc[4];
    #pragma unroll
    for (int q = 0; q < 4; q++) acc[q] = make_float4(0.f, 0.f, 0.f, 0.f);

    const float* base = Q + ((size_t)b * NNODE + chunk * 128 + wid * 32) * DD;
    for (int r = 0; r < 32; r++) {
        const float4* row = (const float4*)(base + (size_t)r * DD);
        float4 v[4];
        float s = 0.f;
        #pragma unroll
        for (int q = 0; q < 4; q++) {
            v[q] = row[lane + 32 * q];
            s += (v[q].x + v[q].y) + (v[q].z + v[q].w);
        }
        #pragma unroll
        for (int o = 16; o; o >>= 1) s += __shfl_xor_sync(0xffffffffu, s, o);
        const float mu = s * (1.f / DD);
        float s2 = 0.f;
        #pragma unroll
        for (int q = 0; q < 4; q++) {
            float dx = v[q].x - mu, dy = v[q].y - mu;
            float dz = v[q].z - mu, dw = v[q].w - mu;
            s2 += (dx * dx + dy * dy) + (dz * dz + dw * dw);
        }
        #pragma unroll
        for (int o = 16; o; o >>= 1) s2 += __shfl_xor_sync(0xffffffffu, s2, o);
        const float rinv = rsqrtf(s2 * (1.f / DD) + 1e-5f);
        #pragma unroll
        for (int q = 0; q < 4; q++) {
            acc[q].x += (v[q].x - mu) * rinv * g4[q].x + b4[q].x;
            acc[q].y += (v[q].y - mu) * rinv * g4[q].y + b4[q].y;
            acc[q].z += (v[q].z - mu) * rinv * g4[q].z + b4[q].z;
            acc[q].w += (v[q].w - mu) * rinv * g4[q].w + b4[q].w;
        }
    }
    const float sc = 1.f / NNODE;
    float* zb = zp + b * DD;
    #pragma unroll
    for (int q = 0; q < 4; q++) {
        int f = 4 * (lane + 32 * q);
        atomicAdd(&zb[f + 0], acc[q].x * sc);
        atomicAdd(&zb[f + 1], acc[q].y * sc);
        atomicAdd(&zb[f + 2], acc[q].z * sc);
        atomicAdd(&zb[f + 3], acc[q].w * sc);
    }
}

// ---------------------------------------------------------------------------
__device__ __forceinline__ float block_sum128(float v, float* red, int t)
{
    #pragma unroll
    for (int off = 16; off; off >>= 1) v += __shfl_down_sync(0xffffffffu, v, off);
    if ((t & 31) == 0) red[t >> 5] = v;
    __syncthreads();
    float s = red[0] + red[1] + red[2] + red[3];
    __syncthreads();
    return s;
}

__global__ void classifier_kernel(const float* __restrict__ zp,
                                  const float* __restrict__ Wc1, const float* __restrict__ bc1,
                                  const float* __restrict__ g1,  const float* __restrict__ t1,
                                  const float* __restrict__ Wc2, const float* __restrict__ bc2,
                                  const float* __restrict__ g2,  const float* __restrict__ t2,
                                  const float* __restrict__ Wc3, const float* __restrict__ bc3,
                                  float* __restrict__ logits)
{
    const int b = blockIdx.x;
    const int t = threadIdx.x;
    __shared__ float z[DD];
    __shared__ float h1[128];
    __shared__ float h2[64];
    __shared__ float red[4];

    #pragma unroll
    for (int i = t; i < DD; i += 128) z[i] = zp[b * DD + i];
    __syncthreads();

    float a1 = bc1[t];
    #pragma unroll 8
    for (int k = 0; k < DD; k++) a1 += z[k] * Wc1[k * 128 + t];
    float mu = block_sum128(a1, red, t) * (1.f / 128.f);
    float d0 = a1 - mu;
    float var = block_sum128(d0 * d0, red, t) * (1.f / 128.f);
    h1[t] = fmaxf(d0 * rsqrtf(var + 1e-5f) * g1[t] + t1[t], 0.f);
    __syncthreads();

    float a2 = 0.f;
    if (t < 64) {
        a2 = bc2[t];
        #pragma unroll 8
        for (int k = 0; k < 128; k++) a2 += h1[k] * Wc2[k * 64 + t];
    }
    float c1 = (t < 64) ? a2 : 0.f;
    float mu2 = block_sum128(c1, red, t) * (1.f / 64.f);
    float d2 = a2 - mu2;
    float c2v = (t < 64) ? d2 * d2 : 0.f;
    float var2 = block_sum128(c2v, red, t) * (1.f / 64.f);
    if (t < 64)
        h2[t] = fmaxf(d2 * rsqrtf(var2 + 1e-5f) * g2[t] + t2[t], 0.f);
    __syncthreads();

    if (t < 4) {
        float a3 = bc3[t];
        #pragma unroll
        for (int k = 0; k < 64; k++) a3 += h2[k] * Wc3[k * 4 + t];
        logits[b * 4 + t] = a3;
    }
}

// ---------------------------------------------------------------------------
extern "C" void kernel_launch(void* const* d_in, const int* in_sizes, int n_in,
                              void* d_out, int out_size)
{
    const float* sc  = (const float*)d_in[0];
    const float* W1  = (const float*)d_in[1];
    const float* b1  = (const float*)d_in[2];
    const float* W2  = (const float*)d_in[3];
    const float* b2  = (const float*)d_in[4];
    const float* lng = (const float*)d_in[5];
    const float* lnb = (const float*)d_in[6];
    const float* Wc1 = (const float*)d_in[7];
    const float* bc1 = (const float*)d_in[8];
    const float* g1  = (const float*)d_in[9];
    const float* t1  = (const float*)d_in[10];
    const float* Wc2 = (const float*)d_in[11];
    const float* bc2 = (const float*)d_in[12];
    const float* g2  = (const float*)d_in[13];
    const float* t2  = (const float*)d_in[14];
    const float* Wc3 = (const float*)d_in[15];
    const float* bc3 = (const float*)d_in[16];
    float* out = (float*)d_out;
    float* zp = out + BB * 4;

    __half *sch, *Ath, *P, *Qh, *W1t, *W2t;
    float *Q32, *dis;
    cudaGetSymbolAddress((void**)&sch, g_sch);
    cudaGetSymbolAddress((void**)&Ath, g_Ath);
    cudaGetSymbolAddress((void**)&P,   g_P);
    cudaGetSymbolAddress((void**)&Qh,  g_Qh);
    cudaGetSymbolAddress((void**)&Q32, g_Q32);
    cudaGetSymbolAddress((void**)&W1t, g_W1t);
    cudaGetSymbolAddress((void**)&W2t, g_W2t);
    cudaGetSymbolAddress((void**)&dis, g_dis);

    // zero zp (output region) + dis accumulator — every replay, in-graph
    zero2_kernel<<<128, 256>>>(zp, BB * DD, dis, BB * NNODE);

    dim3 tb(32, 8);
    sc_prep<<<dim3(32, 32, BB), tb>>>(sc, sch, Ath, dis);
    rsqrt_fin<<<BB * NNODE / 256, 256>>>(dis);
    w_prep<<<dim3(DD / 32, NNODE / 32), tb>>>(W1, W1t, NNODE, DD);
    w_prep<<<dim3(DD / 32, DD / 32), tb>>>(W2, W2t, DD, DD);

    // G1: P[b][n][j] = h(dis[b,j] * (sc@W1)[b,j,n])      (TOUT)
    hgemm<true, false, false, true><<<dim3(4, 256, 1), 256, SMEM_BYTES>>>(
        sch, W1t, P, dis, nullptr, NNODE, NNODE, NNODE, 0, 0, 0, 0, 0);

    // G2: Qh[b][i][n] = h(relu(dis[b,i]*(At@P^T) + b1))
    hgemm<false, true, true, true><<<dim3(4, 8, BB), 256, SMEM_BYTES>>>(
        Ath, P, Qh, dis, b1, NNODE, NNODE, NNODE, DD,
        (size_t)NNODE * NNODE, (size_t)DD * NNODE, (size_t)NNODE * DD, NNODE);

    // G3: P[b][n][j] = h(dis[b,j] * (Qh@W2)[b,j,n])      (TOUT)
    hgemm<true, false, false, true><<<dim3(4, 256, 1), 256, SMEM_BYTES>>>(
        Qh, W2t, P, dis, nullptr, DD, DD, DD, 0, 0, 0, 0, 0);

    // G4: Q32[b][i][n] = dis[b,i]*(At@P^T) + b2  (fp32)
    hgemm<false, false, true, false><<<dim3(4, 8, BB), 256, SMEM_BYTES>>>(
        Ath, P, Q32, dis, b2, NNODE, NNODE, NNODE, DD,
        (size_t)NNODE * NNODE, (size_t)DD * NNODE, (size_t)NNODE * DD, NNODE);

    // fused LN + mean-pool -> zp, then classifier -> out[0:128)
    ln_pool_kernel<<<dim3(8, BB), 128>>>(Q32, lng, lnb, zp);
    classifier_kernel<<<BB, 128>>>(zp, Wc1, bc1, g1, t1,
                                   Wc2, bc2, g2, t2, Wc3, bc3, out);
}

// round 11
// speedup vs baseline: 1.7818x; 1.1171x over previous
#include <cuda_runtime.h>
#include <cuda_fp16.h>
#include <cstdint>
#include <cstddef>

#define BB 32
#define NNODE 1024
#define DD 512

__device__ __half g_sch[(size_t)BB * NNODE * NNODE];   // fp16 sc
__device__ __half g_Ath[(size_t)BB * NNODE * NNODE];   // fp16 sc^T
__device__ __half g_P  [(size_t)BB * NNODE * DD];      // Y1t / Y2t (feat-major fp16)
__device__ __half g_Qh [(size_t)BB * NNODE * DD];      // H1 (fp16)
__device__ float  g_Q32[(size_t)BB * NNODE * DD];      // H2 (fp32)
__device__ __half g_W1t[DD * NNODE];
__device__ __half g_W2t[DD * DD];
__device__ float  g_dis[BB * NNODE];

__device__ __forceinline__ uint32_t smem_u32(const void* p) {
    uint32_t a;
    asm("{ .reg .u64 t; cvta.to.shared.u64 t, %1; cvt.u32.u64 %0, t; }" : "=r"(a) : "l"(p));
    return a;
}
__device__ __forceinline__ void cp16(uint32_t s, const void* g) {
    asm volatile("cp.async.cg.shared.global [%0], [%1], 16;" :: "r"(s), "l"(g));
}
__device__ __forceinline__ void ldm_x4(uint32_t* r, uint32_t a) {
    asm volatile("ldmatrix.sync.aligned.m8n8.x4.shared.b16 {%0,%1,%2,%3}, [%4];"
        : "=r"(r[0]), "=r"(r[1]), "=r"(r[2]), "=r"(r[3]) : "r"(a));
}
__device__ __forceinline__ void ldm_x2(uint32_t& r0, uint32_t& r1, uint32_t a) {
    asm volatile("ldmatrix.sync.aligned.m8n8.x2.shared.b16 {%0,%1}, [%2];"
        : "=r"(r0), "=r"(r1) : "r"(a));
}

// fp16 tile geometry: rows of 32 fp16 (64B) padded to 40 fp16 (80B = 20 banks).
static constexpr int ROW_B   = 80;                  // bytes per smem row
static constexpr int ATILE   = 128 * ROW_B;         // 10240 B
static constexpr int STG     = 2 * ATILE;           // 20480 B per stage
static constexpr int NSTAGE  = 3;
static constexpr int SMEM_BYTES = NSTAGE * STG;     // 61440 B (opt-in)
static constexpr int T_PITCH = 144;                 // fp16 pitch for transpose staging

// ---------------------------------------------------------------------------
// fp16 mma.sync GEMM: CTA tile 128x128, K-chunk 32 (2 x k16), 8 warps (2x4),
// warp tile 64x32, ldmatrix frags, 3-stage cp.async ring, ONE sync per chunk.
// ---------------------------------------------------------------------------
template<bool TOUT, bool RELU, bool HASBIAS, bool OUTHALF>
__global__ __launch_bounds__(256, 2)
void hgemm(const __half* __restrict__ Ap, const __half* __restrict__ Bp,
           void* __restrict__ Cpv, const float* __restrict__ disv,
           const float* __restrict__ bias,
           int K, int lda, int ldb, int ldc,
           size_t sA, size_t sB, size_t sC, size_t sD)
{
    extern __shared__ char smem[];
    const uint32_t sbase = smem_u32(smem);
    const int tid = threadIdx.x;
    const int wid = tid >> 5;
    const int lane = tid & 31;
    const int wm = wid >> 2;
    const int wn = wid & 3;
    const int lrow = lane >> 2;
    const int lcol = lane & 3;
    const int bz = blockIdx.z;
    const int m0 = blockIdx.y * 128;
    const int n0 = blockIdx.x * 128;

    Ap += (size_t)bz * sA;
    Bp += (size_t)bz * sB;
    disv += (size_t)bz * sD;
    if (OUTHALF || TOUT) Cpv = (void*)((__half*)Cpv + (size_t)bz * sC);
    else                 Cpv = (void*)((float*)Cpv + (size_t)bz * sC);

    const int S = K / 32;

    auto load_stage = [&](int k0, uint32_t soff) {
        #pragma unroll
        for (int p = 0; p < 2; p++) {
            int id = tid + 256 * p;
            int row = id >> 2, c = id & 3;
            cp16(sbase + soff + (uint32_t)(row * ROW_B + c * 16),
                 Ap + (size_t)(m0 + row) * lda + k0 + c * 8);
            cp16(sbase + soff + ATILE + (uint32_t)(row * ROW_B + c * 16),
                 Bp + (size_t)(n0 + row) * ldb + k0 + c * 8);
        }
        asm volatile("cp.async.commit_group;" ::: "memory");
    };

    load_stage(0, 0);
    if (S > 1) load_stage(32, STG);

    float acc[4][4][4];
    #pragma unroll
    for (int mi = 0; mi < 4; mi++)
        #pragma unroll
        for (int ni = 0; ni < 4; ni++)
            #pragma unroll
            for (int q = 0; q < 4; q++) acc[mi][ni][q] = 0.f;

    const uint32_t aRowBase = (uint32_t)(wm * 64 + (lane & 15)) * ROW_B
                              + ((uint32_t)(lane >> 4) & 1u) * 16u;
    const uint32_t bRowBase = (uint32_t)(wn * 32 + (lane & 7)) * ROW_B
                              + ((uint32_t)(lane >> 3) & 1u) * 16u;

    for (int s = 0; s < S; s++) {
        if (s + 1 < S) asm volatile("cp.async.wait_group 1;" ::: "memory");
        else           asm volatile("cp.async.wait_group 0;" ::: "memory");
        __syncthreads();            // single barrier per chunk

        const uint32_t aB = sbase + (uint32_t)(s % NSTAGE) * STG;
        const uint32_t bB = aB + ATILE;

        #pragma unroll
        for (int kk = 0; kk < 2; kk++) {
            uint32_t a[4][4];
            #pragma unroll
            for (int mi = 0; mi < 4; mi++)
                ldm_x4(a[mi], aB + aRowBase + (uint32_t)(mi * 16) * ROW_B + kk * 32);
            #pragma unroll
            for (int ni = 0; ni < 4; ni++) {
                uint32_t b0, b1;
                ldm_x2(b0, b1, bB + bRowBase + (uint32_t)(ni * 8) * ROW_B + kk * 32);
                #pragma unroll
                for (int mi = 0; mi < 4; mi++) {
                    asm volatile(
                        "mma.sync.aligned.m16n8k16.row.col.f32.f16.f16.f32 "
                        "{%0,%1,%2,%3}, {%4,%5,%6,%7}, {%8,%9}, {%0,%1,%2,%3};"
                        : "+f"(acc[mi][ni][0]), "+f"(acc[mi][ni][1]),
                          "+f"(acc[mi][ni][2]), "+f"(acc[mi][ni][3])
                        : "r"(a[mi][0]), "r"(a[mi][1]), "r"(a[mi][2]), "r"(a[mi][3]),
                          "r"(b0), "r"(b1));
                }
            }
        }
        // prefetch chunk s+2 into the buffer consumed at iteration s-1:
        // safe — every warp passed this iteration's barrier.
        if (s + 2 < S) load_stage((s + 2) * 32, (uint32_t)((s + 2) % NSTAGE) * STG);
    }

    if (TOUT) {
        __syncthreads();            // guard: smem reused as staging
        __half* sb = (__half*)smem;
        #pragma unroll
        for (int mi = 0; mi < 4; mi++) {
            const int mloc = wm * 64 + mi * 16 + lrow;
            const float d0 = disv[m0 + mloc];
            const float d1 = disv[m0 + mloc + 8];
            #pragma unroll
            for (int ni = 0; ni < 4; ni++) {
                const int nloc = wn * 32 + ni * 8 + 2 * lcol;
                sb[nloc * T_PITCH + mloc]           = __float2half_rn(acc[mi][ni][0] * d0);
                sb[(nloc + 1) * T_PITCH + mloc]     = __float2half_rn(acc[mi][ni][1] * d0);
                sb[nloc * T_PITCH + mloc + 8]       = __float2half_rn(acc[mi][ni][2] * d1);
                sb[(nloc + 1) * T_PITCH + mloc + 8] = __float2half_rn(acc[mi][ni][3] * d1);
            }
        }
        __syncthreads();
        const int b = m0 >> 10;
        const int j0 = m0 & 1023;
        __half* outB = (__half*)Cpv + (size_t)b * DD * 1024 + j0;
        #pragma unroll
        for (int p = 0; p < 8; p++) {
            int id = tid + 256 * p;
            int row = id >> 4, c = id & 15;
            *(uint4*)(outB + (size_t)(n0 + row) * 1024 + c * 8) =
                *(const uint4*)(sb + row * T_PITCH + c * 8);
        }
    } else {
        #pragma unroll
        for (int mi = 0; mi < 4; mi++) {
            const int ml = m0 + wm * 64 + mi * 16 + lrow;
            const float d0 = disv[ml];
            const float d1 = disv[ml + 8];
            #pragma unroll
            for (int ni = 0; ni < 4; ni++) {
                const int n = n0 + wn * 32 + ni * 8 + 2 * lcol;
                float bx = 0.f, by = 0.f;
                if (HASBIAS) { bx = bias[n]; by = bias[n + 1]; }
                float v0 = acc[mi][ni][0] * d0 + bx;
                float v1 = acc[mi][ni][1] * d0 + by;
                float v2 = acc[mi][ni][2] * d1 + bx;
                float v3 = acc[mi][ni][3] * d1 + by;
                if (RELU) {
                    v0 = fmaxf(v0, 0.f); v1 = fmaxf(v1, 0.f);
                    v2 = fmaxf(v2, 0.f); v3 = fmaxf(v3, 0.f);
                }
                if (OUTHALF) {
                    __half* C = (__half*)Cpv;
                    *(__half2*)&C[(size_t)ml * ldc + n] = __floats2half2_rn(v0, v1);
                    *(__half2*)&C[(size_t)(ml + 8) * ldc + n] = __floats2half2_rn(v2, v3);
                } else {
                    float* C = (float*)Cpv;
                    *(float2*)&C[(size_t)ml * ldc + n] = make_float2(v0, v1);
                    *(float2*)&C[(size_t)(ml + 8) * ldc + n] = make_float2(v2, v3);
                }
            }
        }
    }
}

// ---------------------------------------------------------------------------
__global__ void zero2_kernel(float* a, int na, float* c, int nc)
{
    int i = blockIdx.x * 256 + threadIdx.x;
    if (i < na) a[i] = 0.f;
    if (i < nc) c[i] = 0.f;
}

__global__ void sc_prep(const float* __restrict__ sc, __half* __restrict__ sch,
                        __half* __restrict__ Ath, float* __restrict__ dacc)
{
    __shared__ float t[32][33];
    __shared__ float cs[32];
    const size_t zoff = (size_t)blockIdx.z * NNODE * NNODE;
    const int r0 = blockIdx.y * 32, c0 = blockIdx.x * 32;
    const int tx = threadIdx.x, ty = threadIdx.y;
    float v[4];
    #pragma unroll
    for (int q = 0; q < 4; q++) {
        size_t idx = zoff + (size_t)(r0 + ty + q * 8) * NNODE + c0 + tx;
        v[q] = sc[idx];
        sch[idx] = __float2half_rn(v[q]);
        t[ty + q * 8][tx] = v[q];
    }
    if (ty == 0) cs[tx] = 0.f;
    __syncthreads();
    atomicAdd(&cs[tx], (v[0] + v[1]) + (v[2] + v[3]));
    #pragma unroll
    for (int q = 0; q < 4; q++)
        Ath[zoff + (size_t)(c0 + ty + q * 8) * NNODE + r0 + tx] =
            __float2half_rn(t[tx][ty + q * 8]);
    __syncthreads();
    if (ty == 0) atomicAdd(&dacc[(size_t)blockIdx.z * NNODE + c0 + tx], cs[tx]);
}

__global__ void rsqrt_fin(float* __restrict__ dis)
{
    int i = blockIdx.x * 256 + threadIdx.x;
    float s = dis[i];
    dis[i] = (s > 0.f) ? rsqrtf(s) : 0.f;
}

__global__ void w_prep(const float* __restrict__ src, __half* __restrict__ dst,
                       int R, int C)
{
    __shared__ float t[32][33];
    const int r0 = blockIdx.y * 32, c0 = blockIdx.x * 32;
    const int tx = threadIdx.x, ty = threadIdx.y;
    #pragma unroll
    for (int q = 0; q < 4; q++)
        t[ty + q * 8][tx] = src[(size_t)(r0 + ty + q * 8) * C + c0 + tx];
    __syncthreads();
    #pragma unroll
    for (int q = 0; q < 4; q++)
        dst[(size_t)(c0 + ty + q * 8) * R + r0 + tx] = __float2half_rn(t[tx][ty + q * 8]);
}

// ---------------------------------------------------------------------------
__global__ void ln_pool_kernel(const float* __restrict__ Q,
                               const float* __restrict__ g,
                               const float* __restrict__ bta,
                               float* __restrict__ zp)
{
    const int b = blockIdx.y;
    const int chunk = blockIdx.x;
    const int wid = threadIdx.x >> 5;
    const int lane = threadIdx.x & 31;

    float4 g4[4], b4[4];
    #pragma unroll
    for (int q = 0; q < 4; q++) {
        g4[q] = ((const float4*)g)[lane + 32 * q];
        b4[q] = ((const float4*)bta)[lane + 32 * q];
    }
    float4 acc[4];
    #pragma unroll
    for (int q = 0; q < 4; q++) acc[q] = make_float4(0.f, 0.f, 0.f, 0.f);

    const float* base = Q + ((size_t)b * NNODE + chunk * 128 + wid * 32) * DD;
    for (int r = 0; r < 32; r++) {
        const float4* row = (const float4*)(base + (size_t)r * DD);
        float4 v[4];
        float s = 0.f;
        #pragma unroll
        for (int q = 0; q < 4; q++) {
            v[q] = row[lane + 32 * q];
            s += (v[q].x + v[q].y) + (v[q].z + v[q].w);
        }
        #pragma unroll
        for (int o = 16; o; o >>= 1) s += __shfl_xor_sync(0xffffffffu, s, o);
        const float mu = s * (1.f / DD);
        float s2 = 0.f;
        #pragma unroll
        for (int q = 0; q < 4; q++) {
            float dx = v[q].x - mu, dy = v[q].y - mu;
            float dz = v[q].z - mu, dw = v[q].w - mu;
            s2 += (dx * dx + dy * dy) + (dz * dz + dw * dw);
        }
        #pragma unroll
        for (int o = 16; o; o >>= 1) s2 += __shfl_xor_sync(0xffffffffu, s2, o);
        const float rinv = rsqrtf(s2 * (1.f / DD) + 1e-5f);
        #pragma unroll
        for (int q = 0; q < 4; q++) {
            acc[q].x += (v[q].x - mu) * rinv * g4[q].x + b4[q].x;
            acc[q].y += (v[q].y - mu) * rinv * g4[q].y + b4[q].y;
            acc[q].z += (v[q].z - mu) * rinv * g4[q].z + b4[q].z;
            acc[q].w += (v[q].w - mu) * rinv * g4[q].w + b4[q].w;
        }
    }
    const float sc = 1.f / NNODE;
    float* zb = zp + b * DD;
    #pragma unroll
    for (int q = 0; q < 4; q++) {
        int f = 4 * (lane + 32 * q);
        atomicAdd(&zb[f + 0], acc[q].x * sc);
        atomicAdd(&zb[f + 1], acc[q].y * sc);
        atomicAdd(&zb[f + 2], acc[q].z * sc);
        atomicAdd(&zb[f + 3], acc[q].w * sc);
    }
}

// ---------------------------------------------------------------------------
__device__ __forceinline__ float block_sum128(float v, float* red, int t)
{
    #pragma unroll
    for (int off = 16; off; off >>= 1) v += __shfl_down_sync(0xffffffffu, v, off);
    if ((t & 31) == 0) red[t >> 5] = v;
    __syncthreads();
    float s = red[0] + red[1] + red[2] + red[3];
    __syncthreads();
    return s;
}

__global__ void classifier_kernel(const float* __restrict__ zp,
                                  const float* __restrict__ Wc1, const float* __restrict__ bc1,
                                  const float* __restrict__ g1,  const float* __restrict__ t1,
                                  const float* __restrict__ Wc2, const float* __restrict__ bc2,
                                  const float* __restrict__ g2,  const float* __restrict__ t2,
                                  const float* __restrict__ Wc3, const float* __restrict__ bc3,
                                  float* __restrict__ logits)
{
    const int b = blockIdx.x;
    const int t = threadIdx.x;
    __shared__ float z[DD];
    __shared__ float h1[128];
    __shared__ float h2[64];
    __shared__ float red[4];

    #pragma unroll
    for (int i = t; i < DD; i += 128) z[i] = zp[b * DD + i];
    __syncthreads();

    float a1 = bc1[t];
    #pragma unroll 8
    for (int k = 0; k < DD; k++) a1 += z[k] * Wc1[k * 128 + t];
    float mu = block_sum128(a1, red, t) * (1.f / 128.f);
    float d0 = a1 - mu;
    float var = block_sum128(d0 * d0, red, t) * (1.f / 128.f);
    h1[t] = fmaxf(d0 * rsqrtf(var + 1e-5f) * g1[t] + t1[t], 0.f);
    __syncthreads();

    float a2 = 0.f;
    if (t < 64) {
        a2 = bc2[t];
        #pragma unroll 8
        for (int k = 0; k < 128; k++) a2 += h1[k] * Wc2[k * 64 + t];
    }
    float c1 = (t < 64) ? a2 : 0.f;
    float mu2 = block_sum128(c1, red, t) * (1.f / 64.f);
    float d2 = a2 - mu2;
    float c2v = (t < 64) ? d2 * d2 : 0.f;
    float var2 = block_sum128(c2v, red, t) * (1.f / 64.f);
    if (t < 64)
        h2[t] = fmaxf(d2 * rsqrtf(var2 + 1e-5f) * g2[t] + t2[t], 0.f);
    __syncthreads();

    if (t < 4) {
        float a3 = bc3[t];
        #pragma unroll
        for (int k = 0; k < 64; k++) a3 += h2[k] * Wc3[k * 4 + t];
        logits[b * 4 + t] = a3;
    }
}

// ---------------------------------------------------------------------------
extern "C" void kernel_launch(void* const* d_in, const int* in_sizes, int n_in,
                              void* d_out, int out_size)
{
    const float* sc  = (const float*)d_in[0];
    const float* W1  = (const float*)d_in[1];
    const float* b1  = (const float*)d_in[2];
    const float* W2  = (const float*)d_in[3];
    const float* b2  = (const float*)d_in[4];
    const float* lng = (const float*)d_in[5];
    const float* lnb = (const float*)d_in[6];
    const float* Wc1 = (const float*)d_in[7];
    const float* bc1 = (const float*)d_in[8];
    const float* g1  = (const float*)d_in[9];
    const float* t1  = (const float*)d_in[10];
    const float* Wc2 = (const float*)d_in[11];
    const float* bc2 = (const float*)d_in[12];
    const float* g2  = (const float*)d_in[13];
    const float* t2  = (const float*)d_in[14];
    const float* Wc3 = (const float*)d_in[15];
    const float* bc3 = (const float*)d_in[16];
    float* out = (float*)d_out;
    float* zp = out + BB * 4;

    __half *sch, *Ath, *P, *Qh, *W1t, *W2t;
    float *Q32, *dis;
    cudaGetSymbolAddress((void**)&sch, g_sch);
    cudaGetSymbolAddress((void**)&Ath, g_Ath);
    cudaGetSymbolAddress((void**)&P,   g_P);
    cudaGetSymbolAddress((void**)&Qh,  g_Qh);
    cudaGetSymbolAddress((void**)&Q32, g_Q32);
    cudaGetSymbolAddress((void**)&W1t, g_W1t);
    cudaGetSymbolAddress((void**)&W2t, g_W2t);
    cudaGetSymbolAddress((void**)&dis, g_dis);

    cudaFuncSetAttribute(hgemm<true,  false, false, true >,
                         cudaFuncAttributeMaxDynamicSharedMemorySize, SMEM_BYTES);
    cudaFuncSetAttribute(hgemm<false, true,  true,  true >,
                         cudaFuncAttributeMaxDynamicSharedMemorySize, SMEM_BYTES);
    cudaFuncSetAttribute(hgemm<false, false, true,  false>,
                         cudaFuncAttributeMaxDynamicSharedMemorySize, SMEM_BYTES);

    // zero zp (output region) + dis accumulator — every replay, in-graph
    zero2_kernel<<<128, 256>>>(zp, BB * DD, dis, BB * NNODE);

    dim3 tb(32, 8);
    sc_prep<<<dim3(32, 32, BB), tb>>>(sc, sch, Ath, dis);
    rsqrt_fin<<<BB * NNODE / 256, 256>>>(dis);
    w_prep<<<dim3(DD / 32, NNODE / 32), tb>>>(W1, W1t, NNODE, DD);
    w_prep<<<dim3(DD / 32, DD / 32), tb>>>(W2, W2t, DD, DD);

    // G1: P[b][n][j] = h(dis[b,j] * (sc@W1)[b,j,n])      (TOUT)
    hgemm<true, false, false, true><<<dim3(4, 256, 1), 256, SMEM_BYTES>>>(
        sch, W1t, P, dis, nullptr, NNODE, NNODE, NNODE, 0, 0, 0, 0, 0);

    // G2: Qh[b][i][n] = h(relu(dis[b,i]*(At@P^T) + b1))
    hgemm<false, true, true, true><<<dim3(4, 8, BB), 256, SMEM_BYTES>>>(
        Ath, P, Qh, dis, b1, NNODE, NNODE, NNODE, DD,
        (size_t)NNODE * NNODE, (size_t)DD * NNODE, (size_t)NNODE * DD, NNODE);

    // G3: P[b][n][j] = h(dis[b,j] * (Qh@W2)[b,j,n])      (TOUT)
    hgemm<true, false, false, true><<<dim3(4, 256, 1), 256, SMEM_BYTES>>>(
        Qh, W2t, P, dis, nullptr, DD, DD, DD, 0, 0, 0, 0, 0);

    // G4: Q32[b][i][n] = dis[b,i]*(At@P^T) + b2  (fp32)
    hgemm<false, false, true, false><<<dim3(4, 8, BB), 256, SMEM_BYTES>>>(
        Ath, P, Q32, dis, b2, NNODE, NNODE, NNODE, DD,
        (size_t)NNODE * NNODE, (size_t)DD * NNODE, (size_t)NNODE * DD, NNODE);

    // fused LN + mean-pool -> zp, then classifier -> out[0:128)
    ln_pool_kernel<<<dim3(8, BB), 128>>>(Q32, lng, lnb, zp);
    classifier_kernel<<<BB, 128>>>(zp, Wc1, bc1, g1, t1,
                                   Wc2, bc2, g2, t2, Wc3, bc3, out);
}